// round 10
// baseline (speedup 1.0000x reference)
#include <cuda_runtime.h>
#include <math.h>

// ---------------------------------------------------------------------------
// RandomProjection: out[b,o] = mean_s( cos(x[b,s,:], p[o,:]) )
//   kernel 1: m = mean_s(x/||x||) (ticket combine) + p-norms + zero(out)
//   kernel 2: register-tiled GEMM, smem transposed to [k][rows]:
//             2 LDS.128 -> 16 scalar FFMA per k; red.add.v4.f32 epilogue
// ---------------------------------------------------------------------------

#define B_     32
#define S_     512
#define D_     768
#define O_     2048
#define EPS_   1e-8f

#define KSPLIT 24
#define KB     32            // k floats per gemm block
#define OTILE  128           // o rows per gemm block
#define NOT_   (O_ / OTILE)  // 16 o-tiles
#define PMB    36            // msm pitch: [k][32 b + pad]
#define PPO    132           // psm pitch: [k][128 o + pad]

__device__ float g_part[4 * B_ * D_];    // x partials (race-free)
__device__ float g_m[B_ * D_];           // combined mean
__device__ float g_rpn[O_];              // 1/max(||p_o||,eps)
__device__ int   g_ticket[B_];           // kernel1 tickets (zero-init, self-reset)

// ---------------------------------------------------------------------------
// Kernel 1: blocks 0..127: x normalize+reduce; ticket combine -> g_m.
//           blocks 128..143: p-norms (128 rows each) + zero out-slice.
// ---------------------------------------------------------------------------
__global__ void __launch_bounds__(512, 1)
reduce_x_kernel(const float* __restrict__ x, const float* __restrict__ p,
                float* __restrict__ out) {
    const int warp = threadIdx.x >> 5;
    const int lane = threadIdx.x & 31;

    if (blockIdx.x >= 128) {
        const int blk = blockIdx.x - 128;      // 0..15
        {
            float4* o4 = reinterpret_cast<float4*>(out) + blk * 1024;
            o4[threadIdx.x]       = make_float4(0.f, 0.f, 0.f, 0.f);
            o4[threadIdx.x + 512] = make_float4(0.f, 0.f, 0.f, 0.f);
        }
        const int row0 = blk * 128 + warp * 8;
        #pragma unroll 1
        for (int r = 0; r < 8; r++) {
            const int o = row0 + r;
            const float4* prow = reinterpret_cast<const float4*>(p + (size_t)o * D_);
            float ss = 0.f;
            #pragma unroll
            for (int c = 0; c < 6; c++) {
                const float4 v = prow[lane + 32 * c];
                ss += v.x * v.x + v.y * v.y + v.z * v.z + v.w * v.w;
            }
            #pragma unroll
            for (int off = 16; off > 0; off >>= 1)
                ss += __shfl_xor_sync(0xFFFFFFFFu, ss, off);
            if (lane == 0) g_rpn[o] = 1.0f / fmaxf(sqrtf(ss), EPS_);
        }
        return;
    }

    __shared__ float4 sm[16 * 192];
    __shared__ int is_last;

    const int q = blockIdx.x & 3;
    const int b = blockIdx.x >> 2;

    const float4* base = reinterpret_cast<const float4*>(
        x + ((size_t)b * S_ + (size_t)q * 128 + (size_t)warp * 8) * D_);

    const float inv_S = 1.0f / (float)S_;

    float4 acc[6];
    #pragma unroll
    for (int c = 0; c < 6; c++) acc[c] = make_float4(0.f, 0.f, 0.f, 0.f);

    float4 v[6];
    #pragma unroll
    for (int c = 0; c < 6; c++) v[c] = base[lane + 32 * c];

    #pragma unroll
    for (int r = 0; r < 8; r++) {
        float4 vn[6];
        if (r < 7) {
            #pragma unroll
            for (int c = 0; c < 6; c++)
                vn[c] = base[(r + 1) * 192 + lane + 32 * c];
        }
        float ss = 0.f;
        #pragma unroll
        for (int c = 0; c < 6; c++)
            ss += v[c].x * v[c].x + v[c].y * v[c].y
                + v[c].z * v[c].z + v[c].w * v[c].w;
        #pragma unroll
        for (int off = 16; off > 0; off >>= 1)
            ss += __shfl_xor_sync(0xFFFFFFFFu, ss, off);

        const float scale = inv_S / fmaxf(sqrtf(ss), EPS_);
        #pragma unroll
        for (int c = 0; c < 6; c++) {
            acc[c].x += v[c].x * scale;
            acc[c].y += v[c].y * scale;
            acc[c].z += v[c].z * scale;
            acc[c].w += v[c].w * scale;
        }
        if (r < 7) {
            #pragma unroll
            for (int c = 0; c < 6; c++) v[c] = vn[c];
        }
    }

    #pragma unroll
    for (int c = 0; c < 6; c++)
        sm[warp * 192 + lane + 32 * c] = acc[c];
    __syncthreads();

    if (threadIdx.x < 192) {
        float4 s = sm[threadIdx.x];
        #pragma unroll
        for (int w = 1; w < 16; w++) {
            const float4 t = sm[w * 192 + threadIdx.x];
            s.x += t.x; s.y += t.y; s.z += t.z; s.w += t.w;
        }
        reinterpret_cast<float4*>(g_part)[((q * B_ + b) * 192) + threadIdx.x] = s;
    }

    __threadfence();
    __syncthreads();
    if (threadIdx.x == 0)
        is_last = (atomicAdd(&g_ticket[b], 1) == 3) ? 1 : 0;
    __syncthreads();

    if (is_last) {
        __threadfence();
        if (threadIdx.x < 192) {
            const float4* gp = reinterpret_cast<const float4*>(g_part);
            float4 a  = gp[(0 * B_ + b) * 192 + threadIdx.x];
            const float4 b4 = gp[(1 * B_ + b) * 192 + threadIdx.x];
            const float4 c4 = gp[(2 * B_ + b) * 192 + threadIdx.x];
            const float4 d4 = gp[(3 * B_ + b) * 192 + threadIdx.x];
            a.x += b4.x + c4.x + d4.x;
            a.y += b4.y + c4.y + d4.y;
            a.z += b4.z + c4.z + d4.z;
            a.w += b4.w + c4.w + d4.w;
            reinterpret_cast<float4*>(g_m)[b * 192 + threadIdx.x] = a;
        }
        if (threadIdx.x == 0) g_ticket[b] = 0;
    }
}

// ---------------------------------------------------------------------------
// Kernel 2: register-tiled GEMM, transposed smem, vector-red epilogue.
// Grid: 384 = 16 o-tiles x 24 k-splits. Block: 256 threads, ~21.5 KB smem.
// Warp (wb = w>>2, wo = w&3): tile 16b x 32o.
// Lane (bi = l>>3, oj = l&7): thread tile = b[wb*16+bi*4 .. +3] x
//                                          o[ot*128+wo*32+oj*4 .. +3].
// Mainloop per k: 1 LDS.128 (4 consecutive b) + 1 LDS.128 (4 consecutive o)
// -> 16 scalar FFMA. psm pre-scaled by rpn; epilogue = 4x red.add.v4.f32.
// ---------------------------------------------------------------------------
__global__ void __launch_bounds__(256, 4)
gemm_kernel(const float* __restrict__ p, float* __restrict__ out) {
    __shared__ float msm[KB * PMB];     // [k][b]: 32 x 36 = 4.6 KB
    __shared__ float psm[KB * PPO];     // [k][o]: 32 x 132 = 16.9 KB

    const int kq  = blockIdx.x % KSPLIT;
    const int ot  = blockIdx.x / KSPLIT;    // 0..15
    const int tid = threadIdx.x;
    const int k0  = kq * KB;

    // stage m[32 b][32 k] transposed -> msm[k][b]   (256 float4 loads)
    {
        const int b  = tid >> 3;            // 0..31
        const int kc = tid & 7;             // 0..7
        const float4 v = *reinterpret_cast<const float4*>(
            g_m + (size_t)b * D_ + k0 + kc * 4);
        msm[(kc * 4 + 0) * PMB + b] = v.x;
        msm[(kc * 4 + 1) * PMB + b] = v.y;
        msm[(kc * 4 + 2) * PMB + b] = v.z;
        msm[(kc * 4 + 3) * PMB + b] = v.w;
    }
    // stage p[128 o][32 k] * rpn transposed -> psm[k][o]  (1024 float4 loads)
    #pragma unroll
    for (int t = 0; t < 4; t++) {
        const int i  = tid + t * 256;       // 0..1023
        const int o  = i >> 3;              // 0..127
        const int kc = i & 7;               // 0..7
        const float4 v = *reinterpret_cast<const float4*>(
            p + (size_t)(ot * OTILE + o) * D_ + k0 + kc * 4);
        const float rp = g_rpn[ot * OTILE + o];
        psm[(kc * 4 + 0) * PPO + o] = v.x * rp;
        psm[(kc * 4 + 1) * PPO + o] = v.y * rp;
        psm[(kc * 4 + 2) * PPO + o] = v.z * rp;
        psm[(kc * 4 + 3) * PPO + o] = v.w * rp;
    }
    __syncthreads();

    const int warp = tid >> 5;
    const int lane = tid & 31;
    const int wb = warp >> 2;            // 0..1
    const int wo = warp & 3;             // 0..3
    const int bi = lane >> 3;            // 0..3
    const int oj = lane & 7;             // 0..7

    const float* mb = &msm[wb * 16 + bi * 4];
    const float* pb = &psm[wo * 32 + oj * 4];

    float acc[4][4];
    #pragma unroll
    for (int rr = 0; rr < 4; rr++)
        #pragma unroll
        for (int ss = 0; ss < 4; ss++) acc[rr][ss] = 0.f;

    #pragma unroll 8
    for (int k = 0; k < KB; k++) {
        const float4 mv = *reinterpret_cast<const float4*>(mb + k * PMB);
        const float4 pv = *reinterpret_cast<const float4*>(pb + k * PPO);
        acc[0][0] += mv.x * pv.x;  acc[0][1] += mv.x * pv.y;
        acc[0][2] += mv.x * pv.z;  acc[0][3] += mv.x * pv.w;
        acc[1][0] += mv.y * pv.x;  acc[1][1] += mv.y * pv.y;
        acc[1][2] += mv.y * pv.z;  acc[1][3] += mv.y * pv.w;
        acc[2][0] += mv.z * pv.x;  acc[2][1] += mv.z * pv.y;
        acc[2][2] += mv.z * pv.z;  acc[2][3] += mv.z * pv.w;
        acc[3][0] += mv.w * pv.x;  acc[3][1] += mv.w * pv.y;
        acc[3][2] += mv.w * pv.z;  acc[3][3] += mv.w * pv.w;
    }

    // epilogue: 4 consecutive o per b-row -> vectorized global reduction
    const int o0 = ot * OTILE + wo * 32 + oj * 4;
    #pragma unroll
    for (int rr = 0; rr < 4; rr++) {
        float* dst = out + (size_t)(wb * 16 + bi * 4 + rr) * O_ + o0;
        asm volatile("red.global.add.v4.f32 [%0], {%1, %2, %3, %4};"
                     :: "l"(dst), "f"(acc[rr][0]), "f"(acc[rr][1]),
                        "f"(acc[rr][2]), "f"(acc[rr][3])
                     : "memory");
    }
}

// ---------------------------------------------------------------------------
extern "C" void kernel_launch(void* const* d_in, const int* in_sizes, int n_in,
                              void* d_out, int out_size) {
    const float* x = (const float*)d_in[0];   // [32, 512, 768]
    const float* p = (const float*)d_in[1];   // [2048, 768]
    float*     out = (float*)d_out;           // [32, 2048]

    (void)in_sizes; (void)n_in; (void)out_size;

    reduce_x_kernel<<<128 + 16, 512>>>(x, p, out);
    gemm_kernel<<<NOT_ * KSPLIT, 256>>>(p, out);
}